// round 3
// baseline (speedup 1.0000x reference)
#include <cuda_runtime.h>
#include <math.h>

#define DIM 200
#define RED 8
#define JC 20            // columns per chunk
#define NCH 10           // chunks (10*20 = 200)
#define TSTRIDE 20       // smem row stride in floats (80B rows, 16B aligned,
                         // LDS.128 quarter-warp banks 20t mod 32 all distinct)
#define TILEF (DIM * TSTRIDE)   // floats per tile buffer (4000)
#define NJP (DIM / 2)    // 100 j-pairs

// ---- persistent device scratch (no allocations allowed) ----
__device__ float g_kp[2][DIM * RED];        // relu(kernel_p), relu(kernel_n)
__device__ float2 g_kpT[2][NJP * RED];      // [s][jp*8+m] = (kp[2jp][m], kp[2jp+1][m])
__device__ float g_Wc[2 * 128];             // lin2_w @ lin1_w  (2 x 128)
__device__ float g_bc[2];                   // lin2_w @ lin1_b + lin2_b

// kp (row-major) in constant memory: used only in the low-traffic fold step
__constant__ float c_kp[2][DIM * RED];

// ---------------- cp.async helpers ----------------
__device__ __forceinline__ void cp_async16(void* smem_dst, const void* gmem_src) {
    unsigned saddr = (unsigned)__cvta_generic_to_shared(smem_dst);
    asm volatile("cp.async.cg.shared.global [%0], [%1], 16;\n"
                 :: "r"(saddr), "l"(gmem_src) : "memory");
}
__device__ __forceinline__ void cp_commit() {
    asm volatile("cp.async.commit_group;\n" ::: "memory");
}
template <int N>
__device__ __forceinline__ void cp_wait() {
    asm volatile("cp.async.wait_group %0;\n" :: "n"(N) : "memory");
}

// packed dual-FMA: acc.(lo,hi) += a.(lo,hi) * b.(lo,hi)
__device__ __forceinline__ void ffma2(unsigned long long& acc,
                                      unsigned long long a,
                                      unsigned long long b) {
    asm("fma.rn.f32x2 %0, %1, %2, %0;" : "+l"(acc) : "l"(a), "l"(b));
}

// =====================================================================
// Setup: relu(kernels), pair-interleaved kp, fused linear, static loss
// =====================================================================
__global__ void gnn_setup_kernel(
    const float* __restrict__ kp_p, const float* __restrict__ kp_n,
    const float* __restrict__ Wp1, const float* __restrict__ Wp2, const float* __restrict__ Wp3,
    const float* __restrict__ Wn1, const float* __restrict__ Wn2, const float* __restrict__ Wn3,
    const float* __restrict__ lin1_w, const float* __restrict__ lin1_b,
    const float* __restrict__ lin2_w, const float* __restrict__ lin2_b,
    float* __restrict__ out, int loss_idx, int write_loss)
{
    __shared__ float gram_s[128];
    __shared__ float loss_s;
    int tid = threadIdx.x;           // launched with 256 threads exactly
    if (tid == 0) loss_s = 0.f;
    float lp = 0.f;

    // relu kernels + neg penalty + L1(|relu|) penalty
    for (int i = tid; i < DIM * RED; i += 256) {
        float a = kp_p[i], b = kp_n[i];
        float ra = fmaxf(a, 0.f), rb = fmaxf(b, 0.f);
        g_kp[0][i] = ra;
        g_kp[1][i] = rb;
        lp += 0.1f * fmaxf(1e-6f - a, 0.f) + 0.1f * fmaxf(1e-6f - b, 0.f);
        lp += 0.05f * (ra + rb);
    }
    // gcn neg-penalties on the six 8x8 W's
    if (tid < 64) {
        lp += 0.2f * (fmaxf(1e-6f - Wp1[tid], 0.f) + fmaxf(1e-6f - Wp2[tid], 0.f) +
                      fmaxf(1e-6f - Wp3[tid], 0.f) + fmaxf(1e-6f - Wn1[tid], 0.f) +
                      fmaxf(1e-6f - Wn2[tid], 0.f) + fmaxf(1e-6f - Wn3[tid], 0.f));
    }
    __syncthreads();   // g_kp visible to block

    // pair-interleaved transpose for the FFMA2 mainloop
    for (int i = tid; i < 2 * NJP * RED; i += 256) {
        int s  = i / (NJP * RED);
        int r  = i - s * (NJP * RED);
        int jp = r >> 3, m = r & 7;
        g_kpT[s][r] = make_float2(g_kp[s][(2 * jp) * 8 + m],
                                  g_kp[s][(2 * jp + 1) * 8 + m]);
    }

    // gram = kp^T kp, ortho penalty on off-diagonals
    if (tid < 128) {
        int side = tid >> 6, a = (tid >> 3) & 7, b2 = tid & 7;
        const float* kp = g_kp[side];
        float s = 0.f;
        for (int n = 0; n < DIM; n++) s += kp[n * 8 + a] * kp[n * 8 + b2];
        gram_s[tid] = s;
        if (a != b2) lp += 0.2f * s * s;
    }
    __syncthreads();

    // variance of gram diagonal, ddof=1 (0.3 for p-side, 0.5 for n-side)
    if (tid < 2) {
        const float* g = gram_s + tid * 64;
        float mean = 0.f;
        for (int a = 0; a < 8; a++) mean += g[a * 9];
        mean *= 0.125f;
        float v = 0.f;
        for (int a = 0; a < 8; a++) { float d = g[a * 9] - mean; v += d * d; }
        v *= (1.0f / 7.0f);
        lp += (tid ? 0.5f : 0.3f) * v;
    }

    // fused linear:  Wc[c][f] = sum_h lin2_w[c][h] * lin1_w[h][f]
    {
        int c = tid >> 7, f = tid & 127;
        float s = 0.f;
        #pragma unroll
        for (int h = 0; h < 16; h++) s += lin2_w[c * 16 + h] * lin1_w[h * 128 + f];
        g_Wc[tid] = s;
    }
    if (tid < 2) {
        float s = lin2_b[tid];
        #pragma unroll
        for (int h = 0; h < 16; h++) s += lin2_w[tid * 16 + h] * lin1_b[h];
        g_bc[tid] = s;
    }

    atomicAdd(&loss_s, lp);
    __syncthreads();
    if (tid == 0 && write_loss) out[loss_idx] = loss_s;
}

// =====================================================================
// Main: per-batch fused  reduced = kp^T A kp -> 3x GCN -> fused linear
// Double-buffered cp.async staging; kp pairs from smem (broadcast LDS);
// inner product via packed fma.rn.f32x2.
// =====================================================================
__global__ void __launch_bounds__(256, 5) gnn_main_kernel(
    const float* __restrict__ A,
    const float* __restrict__ Wp1, const float* __restrict__ Wp2, const float* __restrict__ Wp3,
    const float* __restrict__ Wn1, const float* __restrict__ Wn2, const float* __restrict__ Wn3,
    float* __restrict__ out)
{
    extern __shared__ float sm[];
    float* tile = sm;                    // 2 * TILEF = 8000 floats (double buffer)
    float* kpp  = tile + 2 * TILEF;      // 1600 floats: kp pairs for current sign
    float* W_s  = kpp + 2 * NJP * RED;   // 192 (3 layers x 64)
    float* Rm   = W_s + 192;             // 64
    float* Msm  = Rm + 64;               // 64
    float* Ysm  = Msm + 64;              // 64
    float* Xsm  = Ysm + 64;              // 64
    float* feat = Xsm + 64;              // 128
    float* part = feat + 128;            // 256
    float* AF   = tile;                  // alias: AF (200x8) reuses buffer 0

    const int b = blockIdx.x;
    const int tid = threadIdx.x;

    for (int s = 0; s < 2; s++) {
        // stage kp pairs (1600 floats = 400 float4) and the three W's
        {
            const float4* src = (const float4*)g_kpT[s];
            float4* dst = (float4*)kpp;
            for (int i = tid; i < NJP * RED / 2; i += 256) dst[i] = src[i];
        }
        if (tid < 192) {
            const float* w;
            if (s == 0) w = (tid < 64) ? Wp1 : ((tid < 128) ? Wp2 : Wp3);
            else        w = (tid < 64) ? Wn1 : ((tid < 128) ? Wn2 : Wn3);
            W_s[tid] = w[tid & 63];
        }

        const float4* Ag = (const float4*)(A + ((size_t)b * 2 + s) * (DIM * DIM));

        unsigned long long acc[8];   // acc[m] = (sum over even j, sum over odd j)
        #pragma unroll
        for (int m = 0; m < 8; m++) acc[m] = 0ull;

        // ---- prologue: stage chunk 0 into buffer 0 ----
        for (int idx = tid; idx < DIM * (JC / 4); idx += 256) {
            int r  = idx / (JC / 4);
            int c4 = idx - r * (JC / 4);
            cp_async16(tile + r * TSTRIDE + c4 * 4, Ag + r * (DIM / 4) + c4);
        }
        cp_commit();

        for (int c = 0; c < NCH; c++) {
            // stage next chunk into the other buffer
            if (c + 1 < NCH) {
                float* dstb = tile + ((c + 1) & 1) * TILEF;
                const int j0q = (c + 1) * (JC / 4);
                for (int idx = tid; idx < DIM * (JC / 4); idx += 256) {
                    int r  = idx / (JC / 4);
                    int c4 = idx - r * (JC / 4);
                    cp_async16(dstb + r * TSTRIDE + c4 * 4,
                               Ag + r * (DIM / 4) + j0q + c4);
                }
                cp_commit();
                cp_wait<1>();   // chunk c complete (chunk c+1 may be in flight)
            } else {
                cp_wait<0>();
            }
            __syncthreads();

            // ---- AF[n,:] += adj[n, c*20:+20] @ kp[c*20:+20, :]  (FFMA2) ----
            if (tid < DIM) {
                const double2* t2 =
                    (const double2*)(tile + (c & 1) * TILEF + tid * TSTRIDE);
                const unsigned long long* kc =
                    (const unsigned long long*)kpp + (size_t)c * (JC / 2) * RED;
                #pragma unroll
                for (int q = 0; q < JC / 4; q++) {
                    double2 a2 = t2[q];            // (A[4q],A[4q+1]) , (A[4q+2],A[4q+3])
                    unsigned long long p0 = __double_as_longlong(a2.x);
                    unsigned long long p1 = __double_as_longlong(a2.y);
                    const unsigned long long* k0 = kc + (2 * q) * RED;
                    const unsigned long long* k1 = kc + (2 * q + 1) * RED;
                    #pragma unroll
                    for (int m = 0; m < 8; m++) ffma2(acc[m], p0, k0[m]);
                    #pragma unroll
                    for (int m = 0; m < 8; m++) ffma2(acc[m], p1, k1[m]);
                }
            }
            __syncthreads();    // buffer (c&1) free for reuse at iter c+1
        }

        // ---- write AF to smem (aliases buffer 0; last compute read buffer 1) ----
        if (tid < DIM) {
            #pragma unroll
            for (int m = 0; m < 8; m++) {
                unsigned long long v = acc[m];
                float lo = __int_as_float((int)(v & 0xffffffffull));
                float hi = __int_as_float((int)(v >> 32));
                AF[tid * 8 + m] = lo + hi;
            }
        }
        __syncthreads();

        // ---- fold: reduced[a,m] = sum_n kp[n,a] * AF[n,m] ----
        {
            int g = tid >> 6, am = tid & 63, a = am >> 3, m = am & 7;
            const float* kpf = c_kp[s];
            float sacc = 0.f;
            int n0 = g * 50;
            #pragma unroll 5
            for (int n = n0; n < n0 + 50; n++)
                sacc = fmaf(kpf[n * 8 + a], AF[n * 8 + m], sacc);
            part[tid] = sacc;
        }
        __syncthreads();
        if (tid < 64) Rm[tid] = part[tid] + part[tid + 64] + part[tid + 128] + part[tid + 192];
        __syncthreads();

        // ---- GCN chain on 8x8 (thread (i,j) per element) ----
        const int i = tid >> 3, j = tid & 7;
        for (int l = 0; l < 3; l++) {
            if (tid < 64) {
                float mv;
                if (l == 0) mv = W_s[tid];                   // x=None -> M = W
                else {
                    mv = 0.f;
                    #pragma unroll
                    for (int k = 0; k < 8; k++)
                        mv = fmaf(Xsm[i * 8 + k], W_s[l * 64 + k * 8 + j], mv);
                }
                Msm[tid] = mv;
            }
            __syncthreads();
            if (tid < 64) {
                float t = 0.f;
                #pragma unroll
                for (int k = 0; k < 8; k++)
                    t = fmaf(Rm[i * 8 + k], Msm[k * 8 + j], t);
                float y = ((i == j) ? 1.0f : 0.0f) + 0.85f * t;
                Ysm[tid] = fmaxf(y, 0.f);
            }
            __syncthreads();
            if (tid < 64) {
                float cs = 0.f;
                #pragma unroll
                for (int r = 0; r < 8; r++) cs += Ysm[r * 8 + j];
                float cm = cs * 0.125f + 1e-6f;
                float z = Ysm[tid] / cm;                     // z >= 0
                Xsm[tid] = z + log1pf(__expf(-z));           // softplus, stable
            }
            __syncthreads();
        }
        if (tid < 64) feat[i * 16 + s * 8 + j] = Xsm[tid];   // concat layout (B,8,16)
        __syncthreads();
    }

    // ---- fused 128 -> 2 linear ----
    if (tid < 2) {
        float acc2 = g_bc[tid];
        const float* w = g_Wc + tid * 128;
        #pragma unroll 8
        for (int f = 0; f < 128; f++) acc2 = fmaf(w[f], feat[f], acc2);
        out[(size_t)b * 2 + tid] = acc2;
    }
}

// =====================================================================
extern "C" void kernel_launch(void* const* d_in, const int* in_sizes, int n_in,
                              void* d_out, int out_size)
{
    const float* A        = (const float*)d_in[0];
    const float* kernel_p = (const float*)d_in[1];
    const float* kernel_n = (const float*)d_in[2];
    const float* Wp1      = (const float*)d_in[3];
    const float* Wp2      = (const float*)d_in[4];
    const float* Wp3      = (const float*)d_in[5];
    const float* Wn1      = (const float*)d_in[6];
    const float* Wn2      = (const float*)d_in[7];
    const float* Wn3      = (const float*)d_in[8];
    const float* lin1_w   = (const float*)d_in[9];
    const float* lin1_b   = (const float*)d_in[10];
    const float* lin2_w   = (const float*)d_in[11];
    const float* lin2_b   = (const float*)d_in[12];
    float* out = (float*)d_out;

    const int B = in_sizes[0] / (2 * DIM * DIM);   // 4096
    const int loss_idx = B * 2;
    const int write_loss = (out_size > loss_idx) ? 1 : 0;

    gnn_setup_kernel<<<1, 256>>>(kernel_p, kernel_n, Wp1, Wp2, Wp3, Wn1, Wn2, Wn3,
                                 lin1_w, lin1_b, lin2_w, lin2_b,
                                 out, loss_idx, write_loss);

    // relu'd kernels -> constant memory for the fold step (async D2D, capture-ok)
    void* gkp_ptr = nullptr;
    cudaGetSymbolAddress(&gkp_ptr, g_kp);
    cudaMemcpyToSymbolAsync(c_kp, gkp_ptr, sizeof(float) * 2 * DIM * RED, 0,
                            cudaMemcpyDeviceToDevice, 0);

    const int smem_floats = 2 * TILEF + 2 * NJP * RED
                          + 192 + 64 + 64 + 64 + 64 + 128 + 256;
    gnn_main_kernel<<<B, 256, smem_floats * sizeof(float)>>>(
        A, Wp1, Wp2, Wp3, Wn1, Wn2, Wn3, out);
}